// round 14
// baseline (speedup 1.0000x reference)
#include <cuda_runtime.h>
#include <math.h>

#define CB 4
#define CN 4096
#define CD 256
#define CH 8
#define CDH 32
#define CML 256
#define CBH (CB*CH)
#define CINNER 256
#define FUSED_SMEM (256*36*4 + 128*40*4)   // 57344 bytes

// ---------------- scratch ----------------------------------------------------
__device__ float g_Y   [CB*CN*CD];
__device__ float g_XN  [CB*CN*CD];
__device__ float g_Q   [CB*CH*CN*CDH];
__device__ float g_K   [CB*CH*CN*CDH];
__device__ float g_V   [CB*CH*CN*CDH];
__device__ float g_QL  [CBH*CML*CDH];
__device__ float g_KL  [CBH*CML*CDH];
__device__ float g_X2  [CBH*CML*CDH];
__device__ float g_A2  [CBH*CML*CML];
__device__ float g_Zb  [CBH*CML*CML];
__device__ float g_Z2  [CBH*CML*CML];
__device__ float g_XZ  [CBH*CML*CML];
__device__ float g_T1  [CBH*CML*CML];
__device__ float g_T2  [CBH*CML*CML];
__device__ float g_X1  [CBH*CML*CDH];
__device__ float g_P3o [4*CBH*CML*CDH];
__device__ float g_P3m [4*CBH*CML];
__device__ float g_P3l [4*CBH*CML];
__device__ float g_OH  [CB*CH*CN*CDH];
__device__ float g_ONBD[CB*CN*CD];
__device__ float g_HID [CB*CN*2*CD];
__device__ float g_pmax[CBH];
__device__ unsigned g_bar;

__device__ __forceinline__ unsigned f2tf(float x) {
    unsigned u;
    asm("cvt.rna.tf32.f32 %0, %1;" : "=r"(u) : "f"(x));
    return u;
}
__device__ __forceinline__ unsigned pack_bf16(float lo, float hi) {
    unsigned r;
    asm("cvt.rn.bf16x2.f32 %0, %1, %2;" : "=r"(r) : "f"(hi), "f"(lo));
    return r;
}
__device__ __forceinline__ float4 ldcg4(const float* p) {
    float4 v;
    asm volatile("ld.global.cg.v4.f32 {%0,%1,%2,%3}, [%4];"
        : "=f"(v.x), "=f"(v.y), "=f"(v.z), "=f"(v.w) : "l"(p));
    return v;
}
__device__ __forceinline__ void mma_tf32(float* c, unsigned a0, unsigned a1,
                                         unsigned a2, unsigned a3,
                                         unsigned b0, unsigned b1) {
    asm volatile(
        "mma.sync.aligned.m16n8k8.row.col.f32.tf32.tf32.f32 "
        "{%0,%1,%2,%3}, {%4,%5,%6,%7}, {%8,%9}, {%0,%1,%2,%3};"
        : "+f"(c[0]), "+f"(c[1]), "+f"(c[2]), "+f"(c[3])
        : "r"(a0), "r"(a1), "r"(a2), "r"(a3), "r"(b0), "r"(b1));
}
__device__ __forceinline__ void mma_bf16(float* c, unsigned a0, unsigned a1,
                                         unsigned a2, unsigned a3,
                                         unsigned b0, unsigned b1) {
    asm volatile(
        "mma.sync.aligned.m16n8k16.row.col.f32.bf16.bf16.f32 "
        "{%0,%1,%2,%3}, {%4,%5,%6,%7}, {%8,%9}, {%0,%1,%2,%3};"
        : "+f"(c[0]), "+f"(c[1]), "+f"(c[2]), "+f"(c[3])
        : "r"(a0), "r"(a1), "r"(a2), "r"(a3), "r"(b0), "r"(b1));
}

// ---------------- layernorm --------------------------------------------------
__global__ void layernorm_kernel(const float* __restrict__ x,
                                 const float* __restrict__ g,
                                 const float* __restrict__ b,
                                 float* __restrict__ out) {
    __shared__ float s[256];
    long long row = blockIdx.x;
    int tid = threadIdx.x;
    float v = x[row*CD + tid];
    s[tid] = v; __syncthreads();
    for (int o = 128; o > 0; o >>= 1) { if (tid < o) s[tid] += s[tid+o]; __syncthreads(); }
    float mu = s[0] * (1.0f/CD);
    __syncthreads();
    float d = v - mu;
    s[tid] = d*d; __syncthreads();
    for (int o = 128; o > 0; o >>= 1) { if (tid < o) s[tid] += s[tid+o]; __syncthreads(); }
    float inv = rsqrtf(s[0]*(1.0f/CD) + 1e-5f);
    out[row*CD + tid] = d * inv * g[tid] + b[tid];
}

// ---------------- tf32 TC GEMM 128x128, BK=32 --------------------------------
// EPI: 0 C=AB | 1 aI-AB | 2 a*AB | 3 C=AB,C2=aI-AB | 4 AB+bias+res
//      5 gelu(AB+bias) | 6 qkv-split
template<int EPI, bool TB>
__global__ void __launch_bounds__(256) tc_gemm_kernel(
    const float* __restrict__ A, const float* __restrict__ B,
    float* __restrict__ C, float* __restrict__ C2, float* __restrict__ C3,
    int M, int N, int K,
    long long sA, long long sB, long long sC,
    float alpha, const float* __restrict__ bias, const float* __restrict__ res)
{
    A += (long long)blockIdx.z * sA;
    B += (long long)blockIdx.z * sB;
    C += (long long)blockIdx.z * sC;
    if (EPI == 3) C2 += (long long)blockIdx.z * sC;

    int m0 = blockIdx.y*128, n0 = blockIdx.x*128;
    __shared__ unsigned As[32][132];
    __shared__ unsigned Bs[32][132];
    int t = threadIdx.x;
    int w = t >> 5, l = t & 31;
    int wm = (w >> 2)*64, wn = (w & 3)*32;
    int grp = l >> 2, qid = l & 3;
    float acc[4][4][4] = {};
    int ar  = t & 127;
    int akg = (t >> 7)*16;
    int bkr = t >> 3;
    int bn4 = (t & 7)*4;

    const float* Arow = A + (long long)(m0+ar)*K;
    const float* Brow = TB ? (B + (long long)(n0+ar)*K) : nullptr;

    float4 pa[4], pb[4];
    #pragma unroll
    for (int i = 0; i < 4; i++) pa[i] = *(const float4*)(Arow + akg + i*4);
    if (!TB) {
        #pragma unroll
        for (int i = 0; i < 4; i++)
            pb[i] = *(const float4*)(B + (long long)bkr*N + n0 + bn4 + i*32);
    } else {
        #pragma unroll
        for (int i = 0; i < 4; i++) pb[i] = *(const float4*)(Brow + akg + i*4);
    }

    for (int k0 = 0; k0 < K; k0 += 32) {
        #pragma unroll
        for (int i = 0; i < 4; i++) {
            As[akg+i*4+0][ar]=f2tf(pa[i].x); As[akg+i*4+1][ar]=f2tf(pa[i].y);
            As[akg+i*4+2][ar]=f2tf(pa[i].z); As[akg+i*4+3][ar]=f2tf(pa[i].w);
        }
        if (!TB) {
            #pragma unroll
            for (int i = 0; i < 4; i++) {
                int n = bn4 + i*32;
                Bs[bkr][n+0]=f2tf(pb[i].x); Bs[bkr][n+1]=f2tf(pb[i].y);
                Bs[bkr][n+2]=f2tf(pb[i].z); Bs[bkr][n+3]=f2tf(pb[i].w);
            }
        } else {
            #pragma unroll
            for (int i = 0; i < 4; i++) {
                Bs[akg+i*4+0][ar]=f2tf(pb[i].x); Bs[akg+i*4+1][ar]=f2tf(pb[i].y);
                Bs[akg+i*4+2][ar]=f2tf(pb[i].z); Bs[akg+i*4+3][ar]=f2tf(pb[i].w);
            }
        }
        __syncthreads();
        if (k0 + 32 < K) {
            int kn = k0 + 32;
            #pragma unroll
            for (int i = 0; i < 4; i++) pa[i] = *(const float4*)(Arow + kn + akg + i*4);
            if (!TB) {
                #pragma unroll
                for (int i = 0; i < 4; i++)
                    pb[i] = *(const float4*)(B + (long long)(kn+bkr)*N + n0 + bn4 + i*32);
            } else {
                #pragma unroll
                for (int i = 0; i < 4; i++) pb[i] = *(const float4*)(Brow + kn + akg + i*4);
            }
        }
        #pragma unroll
        for (int ks = 0; ks < 4; ks++) {
            int kb = ks*8;
            unsigned af[4][4], bf[4][2];
            #pragma unroll
            for (int mi = 0; mi < 4; mi++) {
                int mb = wm + mi*16;
                af[mi][0] = As[kb+qid  ][mb+grp  ];
                af[mi][1] = As[kb+qid  ][mb+grp+8];
                af[mi][2] = As[kb+qid+4][mb+grp  ];
                af[mi][3] = As[kb+qid+4][mb+grp+8];
            }
            #pragma unroll
            for (int ni = 0; ni < 4; ni++) {
                int nb = wn + ni*8;
                bf[ni][0] = Bs[kb+qid  ][nb+grp];
                bf[ni][1] = Bs[kb+qid+4][nb+grp];
            }
            #pragma unroll
            for (int mi = 0; mi < 4; mi++)
                #pragma unroll
                for (int ni = 0; ni < 4; ni++)
                    mma_tf32(acc[mi][ni], af[mi][0], af[mi][1], af[mi][2], af[mi][3],
                             bf[ni][0], bf[ni][1]);
        }
        __syncthreads();
    }
    #pragma unroll
    for (int mi = 0; mi < 4; mi++)
        #pragma unroll
        for (int ni = 0; ni < 4; ni++)
            #pragma unroll
            for (int r = 0; r < 4; r++) {
                int gm = m0 + wm + mi*16 + grp + ((r >= 2) ? 8 : 0);
                int gn = n0 + wn + ni*8 + 2*qid + (r & 1);
                float v = acc[mi][ni][r];
                long long off = (long long)gm*N + gn;
                if (EPI == 6) {
                    int which = gn >> 8;
                    int h = (gn >> 5) & 7;
                    int d = gn & 31;
                    int b = gm >> 12;
                    int n_tok = gm & 4095;
                    long long dst = ((((long long)b*CH + h)*CN) + n_tok)*CDH + d;
                    if (which == 0)      C [dst] = v * 0.17677669529663687f;
                    else if (which == 1) C2[dst] = v;
                    else                 C3[dst] = v;
                    continue;
                }
                if (EPI == 1)      C[off] = ((gm==gn)?alpha:0.0f) - v;
                else if (EPI == 2) C[off] = alpha * v;
                else if (EPI == 4) C[off] = v + bias[gn] + res[off];
                else if (EPI == 5) { v += bias[gn]; C[off] = 0.5f*v*(1.0f + erff(v*0.70710678118654752f)); }
                else               C[off] = v;
                if (EPI == 3)      C2[off] = ((gm==gn)?alpha:0.0f) - v;
            }
}

// ---------------- persistent pinv: 5 bf16 NS iterations, 1 launch ------------
// grid MUST be 128 blocks (<= SM count) -> all co-resident, spin barrier safe.
// Each phase: every block computes one 128x128 tile (128 tiles = 2x2x32 batch).
// All A/B reads via ld.global.cg (L2) - L1 is stale across phases in-launch.
__global__ void __launch_bounds__(256) pinv_persist_kernel(
    const float* __restrict__ A2g, float* __restrict__ z0b, float* __restrict__ z1b,
    float* __restrict__ XZg, float* __restrict__ T1g, float* __restrict__ T2g,
    int niter)
{
    __shared__ unsigned As[16][132];
    __shared__ unsigned Bs[16][132];
    const long long MM = (long long)CML*CML;
    int tile = blockIdx.x;
    long long off = (long long)(tile >> 2) * MM;
    int m0 = ((tile >> 1) & 1) * 128;
    int n0 = (tile & 1) * 128;
    const float* A2 = A2g + off;
    float* z0 = z0b + off; float* z1 = z1b + off;
    float* XZ = XZg + off; float* T1 = T1g + off; float* T2 = T2g + off;

    int t = threadIdx.x;
    int w = t >> 5, l = t & 31;
    int wm = (w >> 2)*64, wn = (w & 3)*32;
    int grp = l >> 2, qid = l & 3;
    int ar  = t & 127, akg = (t >> 7)*16;
    int bpr = t >> 4,  bn8 = (t & 15)*8;
    unsigned bar_target = 0;

    for (int it = 0; it < niter; it++) {
        float* zc = (it & 1) ? z1 : z0;
        float* zn = (it & 1) ? z0 : z1;
        for (int ph = 0; ph < 4; ph++) {
            const float* A = (ph == 0) ? A2 : ((ph == 3) ? zc : XZ);
            const float* B = (ph == 0) ? zc : ((ph == 1) ? T1 : ((ph == 2) ? T2 : T1));
            float acc[4][4][4] = {};
            for (int k0 = 0; k0 < 256; k0 += 32) {
                const float* Arow = A + (long long)(m0+ar)*256 + k0 + akg;
                float4 a0 = ldcg4(Arow), a1 = ldcg4(Arow+4);
                float4 a2 = ldcg4(Arow+8), a3 = ldcg4(Arow+12);
                int ap = akg >> 1;
                As[ap+0][ar]=pack_bf16(a0.x,a0.y); As[ap+1][ar]=pack_bf16(a0.z,a0.w);
                As[ap+2][ar]=pack_bf16(a1.x,a1.y); As[ap+3][ar]=pack_bf16(a1.z,a1.w);
                As[ap+4][ar]=pack_bf16(a2.x,a2.y); As[ap+5][ar]=pack_bf16(a2.z,a2.w);
                As[ap+6][ar]=pack_bf16(a3.x,a3.y); As[ap+7][ar]=pack_bf16(a3.z,a3.w);
                const float* b0p = B + (long long)(k0 + 2*bpr)*256 + n0 + bn8;
                const float* b1p = b0p + 256;
                float4 b0a = ldcg4(b0p), b0b = ldcg4(b0p+4);
                float4 b1a = ldcg4(b1p), b1b = ldcg4(b1p+4);
                Bs[bpr][bn8+0]=pack_bf16(b0a.x,b1a.x);
                Bs[bpr][bn8+1]=pack_bf16(b0a.y,b1a.y);
                Bs[bpr][bn8+2]=pack_bf16(b0a.z,b1a.z);
                Bs[bpr][bn8+3]=pack_bf16(b0a.w,b1a.w);
                Bs[bpr][bn8+4]=pack_bf16(b0b.x,b1b.x);
                Bs[bpr][bn8+5]=pack_bf16(b0b.y,b1b.y);
                Bs[bpr][bn8+6]=pack_bf16(b0b.z,b1b.z);
                Bs[bpr][bn8+7]=pack_bf16(b0b.w,b1b.w);
                __syncthreads();
                #pragma unroll
                for (int kc = 0; kc < 2; kc++) {
                    int p0 = kc*8;
                    unsigned af[4][4], bf[4][2];
                    #pragma unroll
                    for (int mi = 0; mi < 4; mi++) {
                        int mb = wm + mi*16;
                        af[mi][0] = As[p0+qid  ][mb+grp  ];
                        af[mi][1] = As[p0+qid  ][mb+grp+8];
                        af[mi][2] = As[p0+qid+4][mb+grp  ];
                        af[mi][3] = As[p0+qid+4][mb+grp+8];
                    }
                    #pragma unroll
                    for (int ni = 0; ni < 4; ni++) {
                        int nb = wn + ni*8;
                        bf[ni][0] = Bs[p0+qid  ][nb+grp];
                        bf[ni][1] = Bs[p0+qid+4][nb+grp];
                    }
                    #pragma unroll
                    for (int mi = 0; mi < 4; mi++)
                        #pragma unroll
                        for (int ni = 0; ni < 4; ni++)
                            mma_bf16(acc[mi][ni], af[mi][0], af[mi][1], af[mi][2], af[mi][3],
                                     bf[ni][0], bf[ni][1]);
                }
                __syncthreads();
            }
            // epilogue
            #pragma unroll
            for (int mi = 0; mi < 4; mi++)
                #pragma unroll
                for (int ni = 0; ni < 4; ni++)
                    #pragma unroll
                    for (int r = 0; r < 4; r++) {
                        int gm = m0 + wm + mi*16 + grp + ((r >= 2) ? 8 : 0);
                        int gn = n0 + wn + ni*8 + 2*qid + (r & 1);
                        float v = acc[mi][ni][r];
                        long long o = (long long)gm*256 + gn;
                        float dg = (gm == gn) ? 1.0f : 0.0f;
                        if (ph == 0)      { XZ[o] = v; T1[o] = 7.0f*dg - v; }
                        else if (ph == 1) T2[o] = 15.0f*dg - v;
                        else if (ph == 2) T1[o] = 13.0f*dg - v;
                        else              zn[o] = 0.25f*v;
                    }
            // global barrier (skip after very last phase)
            if (!(it == niter-1 && ph == 3)) {
                bar_target += 128;
                __syncthreads();
                if (t == 0) {
                    __threadfence();
                    atomicAdd(&g_bar, 1u);
                    while (*((volatile unsigned*)&g_bar) < bar_target) {}
                    __threadfence();
                }
                __syncthreads();
            }
        }
    }
}

// ---------------- fused attn2: A2 = softmax(QL @ KL^T), one kernel -----------
__global__ void __launch_bounds__(256) fused_attn2_kernel(
    const float* __restrict__ QL, const float* __restrict__ KL,
    float* __restrict__ A2)
{
    __shared__ unsigned sKL[256][36];
    int bh = blockIdx.y;
    int m0 = blockIdx.x * 128;
    int t = threadIdx.x;
    int w = t >> 5, l = t & 31;
    int grp = l >> 2, qid = l & 3;
    const float* Qp  = QL + ((long long)bh*CML + m0)*CDH;
    const float* KLp = KL + (long long)bh*CML*CDH;
    float* Op = A2 + (long long)bh*CML*CML;

    #pragma unroll
    for (int i = 0; i < 8; i++) {
        int e = t + i*256;
        int n = e >> 3, kq = (e & 7)*4;
        float4 v = *(const float4*)(KLp + n*32 + kq);
        sKL[n][kq+0]=f2tf(v.x); sKL[n][kq+1]=f2tf(v.y);
        sKL[n][kq+2]=f2tf(v.z); sKL[n][kq+3]=f2tf(v.w);
    }
    __syncthreads();

    int mr = w*16;
    unsigned aq[4][4];
    #pragma unroll
    for (int ks = 0; ks < 4; ks++) {
        int k = ks*8;
        aq[ks][0] = f2tf(Qp[(mr+grp  )*32 + k+qid  ]);
        aq[ks][1] = f2tf(Qp[(mr+grp+8)*32 + k+qid  ]);
        aq[ks][2] = f2tf(Qp[(mr+grp  )*32 + k+qid+4]);
        aq[ks][3] = f2tf(Qp[(mr+grp+8)*32 + k+qid+4]);
    }
    float acc[32][4];
    #pragma unroll
    for (int ni = 0; ni < 32; ni++) { acc[ni][0]=0.f; acc[ni][1]=0.f; acc[ni][2]=0.f; acc[ni][3]=0.f; }
    #pragma unroll
    for (int ni = 0; ni < 32; ni++)
        #pragma unroll
        for (int ks = 0; ks < 4; ks++) {
            unsigned b0 = sKL[ni*8+grp][ks*8+qid];
            unsigned b1 = sKL[ni*8+grp][ks*8+qid+4];
            mma_tf32(acc[ni], aq[ks][0], aq[ks][1], aq[ks][2], aq[ks][3], b0, b1);
        }
    float m1 = -3.4e38f, m2 = -3.4e38f;
    #pragma unroll
    for (int ni = 0; ni < 32; ni++) {
        m1 = fmaxf(m1, fmaxf(acc[ni][0], acc[ni][1]));
        m2 = fmaxf(m2, fmaxf(acc[ni][2], acc[ni][3]));
    }
    m1 = fmaxf(m1, __shfl_xor_sync(0xffffffffu, m1, 1));
    m1 = fmaxf(m1, __shfl_xor_sync(0xffffffffu, m1, 2));
    m2 = fmaxf(m2, __shfl_xor_sync(0xffffffffu, m2, 1));
    m2 = fmaxf(m2, __shfl_xor_sync(0xffffffffu, m2, 2));
    float s1 = 0.f, s2 = 0.f;
    #pragma unroll
    for (int ni = 0; ni < 32; ni++) {
        acc[ni][0] = __expf(acc[ni][0]-m1); acc[ni][1] = __expf(acc[ni][1]-m1);
        acc[ni][2] = __expf(acc[ni][2]-m2); acc[ni][3] = __expf(acc[ni][3]-m2);
        s1 += acc[ni][0] + acc[ni][1];
        s2 += acc[ni][2] + acc[ni][3];
    }
    s1 += __shfl_xor_sync(0xffffffffu, s1, 1);
    s1 += __shfl_xor_sync(0xffffffffu, s1, 2);
    s2 += __shfl_xor_sync(0xffffffffu, s2, 1);
    s2 += __shfl_xor_sync(0xffffffffu, s2, 2);
    float i1 = 1.0f/s1, i2 = 1.0f/s2;
    int r1 = m0 + mr + grp, r2 = r1 + 8;
    #pragma unroll
    for (int ni = 0; ni < 32; ni++) {
        int cb0 = ni*8 + 2*qid, cb1 = cb0 + 1;
        Op[(long long)r1*CML + cb0] = acc[ni][0]*i1;
        Op[(long long)r1*CML + cb1] = acc[ni][1]*i1;
        Op[(long long)r2*CML + cb0] = acc[ni][2]*i2;
        Op[(long long)r2*CML + cb1] = acc[ni][3]*i2;
    }
}

// ---------------- fused attn1: OH = softmax(Q @ KL^T) @ X2 -------------------
__global__ void __launch_bounds__(256) fused_attn1_kernel(
    const float* __restrict__ Q, const float* __restrict__ KL,
    const float* __restrict__ X2, float* __restrict__ OH)
{
    extern __shared__ unsigned smemu[];
    unsigned (*sKL)[36]  = (unsigned(*)[36])smemu;
    unsigned (*sX2p)[40] = (unsigned(*)[40])(smemu + 256*36);
    int bh = blockIdx.y;
    int m0 = blockIdx.x * 128;
    int t = threadIdx.x;
    int w = t >> 5, l = t & 31;
    int grp = l >> 2, qid = l & 3;
    const float* Qp  = Q  + ((long long)bh*CN + m0)*CDH;
    const float* KLp = KL + (long long)bh*CML*CDH;
    const float* Xp  = X2 + (long long)bh*CML*CDH;

    #pragma unroll
    for (int i = 0; i < 8; i++) {
        int e = t + i*256;
        int n = e >> 3, kq = (e & 7)*4;
        float4 v = *(const float4*)(KLp + n*32 + kq);
        sKL[n][kq+0]=f2tf(v.x); sKL[n][kq+1]=f2tf(v.y);
        sKL[n][kq+2]=f2tf(v.z); sKL[n][kq+3]=f2tf(v.w);
    }
    #pragma unroll
    for (int i = 0; i < 4; i++) {
        int e = t + i*256;
        int kh = e >> 3, nq = (e & 7)*4;
        float4 v0 = *(const float4*)(Xp + (2*kh  )*32 + nq);
        float4 v1 = *(const float4*)(Xp + (2*kh+1)*32 + nq);
        sX2p[kh][nq+0] = pack_bf16(v0.x, v1.x);
        sX2p[kh][nq+1] = pack_bf16(v0.y, v1.y);
        sX2p[kh][nq+2] = pack_bf16(v0.z, v1.z);
        sX2p[kh][nq+3] = pack_bf16(v0.w, v1.w);
    }
    __syncthreads();

    int mr = w*16;
    unsigned aq[4][4];
    #pragma unroll
    for (int ks = 0; ks < 4; ks++) {
        int k = ks*8;
        aq[ks][0] = f2tf(Qp[(mr+grp  )*32 + k+qid  ]);
        aq[ks][1] = f2tf(Qp[(mr+grp+8)*32 + k+qid  ]);
        aq[ks][2] = f2tf(Qp[(mr+grp  )*32 + k+qid+4]);
        aq[ks][3] = f2tf(Qp[(mr+grp+8)*32 + k+qid+4]);
    }
    float acc[32][4];
    #pragma unroll
    for (int ni = 0; ni < 32; ni++) { acc[ni][0]=0.f; acc[ni][1]=0.f; acc[ni][2]=0.f; acc[ni][3]=0.f; }
    #pragma unroll
    for (int ni = 0; ni < 32; ni++)
        #pragma unroll
        for (int ks = 0; ks < 4; ks++) {
            unsigned b0 = sKL[ni*8+grp][ks*8+qid];
            unsigned b1 = sKL[ni*8+grp][ks*8+qid+4];
            mma_tf32(acc[ni], aq[ks][0], aq[ks][1], aq[ks][2], aq[ks][3], b0, b1);
        }
    float m1 = -3.4e38f, m2 = -3.4e38f;
    #pragma unroll
    for (int ni = 0; ni < 32; ni++) {
        m1 = fmaxf(m1, fmaxf(acc[ni][0], acc[ni][1]));
        m2 = fmaxf(m2, fmaxf(acc[ni][2], acc[ni][3]));
    }
    m1 = fmaxf(m1, __shfl_xor_sync(0xffffffffu, m1, 1));
    m1 = fmaxf(m1, __shfl_xor_sync(0xffffffffu, m1, 2));
    m2 = fmaxf(m2, __shfl_xor_sync(0xffffffffu, m2, 1));
    m2 = fmaxf(m2, __shfl_xor_sync(0xffffffffu, m2, 2));
    float s1 = 0.f, s2 = 0.f;
    #pragma unroll
    for (int ni = 0; ni < 32; ni++) {
        acc[ni][0] = __expf(acc[ni][0]-m1); acc[ni][1] = __expf(acc[ni][1]-m1);
        acc[ni][2] = __expf(acc[ni][2]-m2); acc[ni][3] = __expf(acc[ni][3]-m2);
        s1 += acc[ni][0] + acc[ni][1];
        s2 += acc[ni][2] + acc[ni][3];
    }
    s1 += __shfl_xor_sync(0xffffffffu, s1, 1);
    s1 += __shfl_xor_sync(0xffffffffu, s1, 2);
    s2 += __shfl_xor_sync(0xffffffffu, s2, 1);
    s2 += __shfl_xor_sync(0xffffffffu, s2, 2);
    float i1 = 1.0f/s1, i2 = 1.0f/s2;
    #pragma unroll
    for (int ni = 0; ni < 32; ni++) {
        acc[ni][0]*=i1; acc[ni][1]*=i1; acc[ni][2]*=i2; acc[ni][3]*=i2;
    }
    float ao[4][4] = {};
    #pragma unroll
    for (int c = 0; c < 16; c++) {
        unsigned a0 = pack_bf16(acc[2*c  ][0], acc[2*c  ][1]);
        unsigned a1 = pack_bf16(acc[2*c  ][2], acc[2*c  ][3]);
        unsigned a2 = pack_bf16(acc[2*c+1][0], acc[2*c+1][1]);
        unsigned a3 = pack_bf16(acc[2*c+1][2], acc[2*c+1][3]);
        #pragma unroll
        for (int j = 0; j < 4; j++) {
            unsigned b0 = sX2p[c*8+qid  ][j*8+grp];
            unsigned b1 = sX2p[c*8+qid+4][j*8+grp];
            mma_bf16(ao[j], a0, a1, a2, a3, b0, b1);
        }
    }
    float* Op = OH + ((long long)bh*CN + m0 + mr)*CDH;
    #pragma unroll
    for (int j = 0; j < 4; j++) {
        Op[(grp  )*32 + j*8+2*qid  ] = ao[j][0];
        Op[(grp  )*32 + j*8+2*qid+1] = ao[j][1];
        Op[(grp+8)*32 + j*8+2*qid  ] = ao[j][2];
        Op[(grp+8)*32 + j*8+2*qid+1] = ao[j][3];
    }
}

// ---------------- fused attn3 split over 4 key-chunks ------------------------
__global__ void __launch_bounds__(256) fused_attn3_split_kernel(
    const float* __restrict__ QL, const float* __restrict__ Kg,
    const float* __restrict__ V,
    float* __restrict__ po, float* __restrict__ pm, float* __restrict__ pl)
{
    extern __shared__ unsigned smemu[];
    unsigned (*sK)[36]  = (unsigned(*)[36])smemu;
    unsigned (*sVp)[40] = (unsigned(*)[40])(smemu + 256*36);
    int bh = blockIdx.z;
    int chunk = blockIdx.y;
    int m0 = blockIdx.x * 128;
    int t = threadIdx.x;
    int w = t >> 5, l = t & 31;
    int grp = l >> 2, qid = l & 3;
    const float* Qp = QL + ((long long)bh*CML + m0)*CDH;

    int mr = w*16;
    unsigned aq[4][4];
    #pragma unroll
    for (int ks = 0; ks < 4; ks++) {
        int k = ks*8;
        aq[ks][0] = f2tf(Qp[(mr+grp  )*32 + k+qid  ]);
        aq[ks][1] = f2tf(Qp[(mr+grp+8)*32 + k+qid  ]);
        aq[ks][2] = f2tf(Qp[(mr+grp  )*32 + k+qid+4]);
        aq[ks][3] = f2tf(Qp[(mr+grp+8)*32 + k+qid+4]);
    }
    float ao[4][4] = {};
    float m1 = -3.4e38f, m2 = -3.4e38f, l1 = 0.f, l2 = 0.f;

    for (int kc = chunk*4; kc < chunk*4 + 4; kc++) {
        __syncthreads();
        const float* Kp = Kg + ((long long)bh*CN + kc*256)*CDH;
        const float* Vp = V  + ((long long)bh*CN + kc*256)*CDH;
        #pragma unroll
        for (int i = 0; i < 8; i++) {
            int e = t + i*256;
            int n = e >> 3, kq = (e & 7)*4;
            float4 v = *(const float4*)(Kp + n*32 + kq);
            sK[n][kq+0]=f2tf(v.x); sK[n][kq+1]=f2tf(v.y);
            sK[n][kq+2]=f2tf(v.z); sK[n][kq+3]=f2tf(v.w);
        }
        #pragma unroll
        for (int i = 0; i < 4; i++) {
            int e = t + i*256;
            int kh = e >> 3, nq = (e & 7)*4;
            float4 v0 = *(const float4*)(Vp + (2*kh  )*32 + nq);
            float4 v1 = *(const float4*)(Vp + (2*kh+1)*32 + nq);
            sVp[kh][nq+0] = pack_bf16(v0.x, v1.x);
            sVp[kh][nq+1] = pack_bf16(v0.y, v1.y);
            sVp[kh][nq+2] = pack_bf16(v0.z, v1.z);
            sVp[kh][nq+3] = pack_bf16(v0.w, v1.w);
        }
        __syncthreads();
        float acc[32][4];
        #pragma unroll
        for (int ni = 0; ni < 32; ni++) { acc[ni][0]=0.f; acc[ni][1]=0.f; acc[ni][2]=0.f; acc[ni][3]=0.f; }
        #pragma unroll
        for (int ni = 0; ni < 32; ni++)
            #pragma unroll
            for (int ks = 0; ks < 4; ks++) {
                unsigned b0 = sK[ni*8+grp][ks*8+qid];
                unsigned b1 = sK[ni*8+grp][ks*8+qid+4];
                mma_tf32(acc[ni], aq[ks][0], aq[ks][1], aq[ks][2], aq[ks][3], b0, b1);
            }
        float c1 = -3.4e38f, c2 = -3.4e38f;
        #pragma unroll
        for (int ni = 0; ni < 32; ni++) {
            c1 = fmaxf(c1, fmaxf(acc[ni][0], acc[ni][1]));
            c2 = fmaxf(c2, fmaxf(acc[ni][2], acc[ni][3]));
        }
        c1 = fmaxf(c1, __shfl_xor_sync(0xffffffffu, c1, 1));
        c1 = fmaxf(c1, __shfl_xor_sync(0xffffffffu, c1, 2));
        c2 = fmaxf(c2, __shfl_xor_sync(0xffffffffu, c2, 1));
        c2 = fmaxf(c2, __shfl_xor_sync(0xffffffffu, c2, 2));
        float n1 = fmaxf(m1, c1), n2 = fmaxf(m2, c2);
        float sc1 = __expf(m1 - n1), sc2 = __expf(m2 - n2);
        float s1 = 0.f, s2 = 0.f;
        #pragma unroll
        for (int ni = 0; ni < 32; ni++) {
            acc[ni][0] = __expf(acc[ni][0]-n1); acc[ni][1] = __expf(acc[ni][1]-n1);
            acc[ni][2] = __expf(acc[ni][2]-n2); acc[ni][3] = __expf(acc[ni][3]-n2);
            s1 += acc[ni][0] + acc[ni][1];
            s2 += acc[ni][2] + acc[ni][3];
        }
        s1 += __shfl_xor_sync(0xffffffffu, s1, 1);
        s1 += __shfl_xor_sync(0xffffffffu, s1, 2);
        s2 += __shfl_xor_sync(0xffffffffu, s2, 1);
        s2 += __shfl_xor_sync(0xffffffffu, s2, 2);
        l1 = l1*sc1 + s1; l2 = l2*sc2 + s2;
        m1 = n1; m2 = n2;
        #pragma unroll
        for (int j = 0; j < 4; j++) {
            ao[j][0]*=sc1; ao[j][1]*=sc1; ao[j][2]*=sc2; ao[j][3]*=sc2;
        }
        #pragma unroll
        for (int c = 0; c < 16; c++) {
            unsigned a0 = pack_bf16(acc[2*c  ][0], acc[2*c  ][1]);
            unsigned a1 = pack_bf16(acc[2*c  ][2], acc[2*c  ][3]);
            unsigned a2 = pack_bf16(acc[2*c+1][0], acc[2*c+1][1]);
            unsigned a3 = pack_bf16(acc[2*c+1][2], acc[2*c+1][3]);
            #pragma unroll
            for (int j = 0; j < 4; j++) {
                unsigned b0 = sVp[c*8+qid  ][j*8+grp];
                unsigned b1 = sVp[c*8+qid+4][j*8+grp];
                mma_bf16(ao[j], a0, a1, a2, a3, b0, b1);
            }
        }
    }
    int r1 = m0 + mr + grp, r2 = r1 + 8;
    long long sb = ((long long)chunk*CBH + bh)*CML;
    float* Op  = po + (sb + r1)*CDH;
    float* Op2 = po + (sb + r2)*CDH;
    #pragma unroll
    for (int j = 0; j < 4; j++) {
        Op [j*8+2*qid  ] = ao[j][0];
        Op [j*8+2*qid+1] = ao[j][1];
        Op2[j*8+2*qid  ] = ao[j][2];
        Op2[j*8+2*qid+1] = ao[j][3];
    }
    if (qid == 0) {
        pm[sb + r1] = m1; pl[sb + r1] = l1;
        pm[sb + r2] = m2; pl[sb + r2] = l2;
    }
}

__global__ void attn3_merge_kernel(
    const float* __restrict__ po, const float* __restrict__ pm,
    const float* __restrict__ pl, float* __restrict__ X1)
{
    long long idx = (long long)blockIdx.x*256 + threadIdx.x;
    int d = (int)(idx & 31);
    int r = (int)((idx >> 5) & 255);
    int bh = (int)(idx >> 13);
    float m = -3.4e38f;
    #pragma unroll
    for (int c = 0; c < 4; c++)
        m = fmaxf(m, pm[((long long)c*CBH + bh)*CML + r]);
    float l = 0.f, o = 0.f;
    #pragma unroll
    for (int c = 0; c < 4; c++) {
        long long s = ((long long)c*CBH + bh)*CML + r;
        float e = __expf(pm[s] - m);
        l += pl[s] * e;
        o += po[s*CDH + d] * e;
    }
    X1[idx] = o / l;
}

// ---------------- narrow-N (N=32) tf32 TC GEMM -------------------------------
__global__ void __launch_bounds__(256) tc_n32_kernel(
    const float* __restrict__ A, const float* __restrict__ B, float* __restrict__ C,
    int M, int K, long long sA, long long sB, long long sC)
{
    A += (long long)blockIdx.z * sA;
    B += (long long)blockIdx.z * sB;
    C += (long long)blockIdx.z * sC;
    __shared__ unsigned As[32][132];
    __shared__ unsigned Bs[32][36];
    int t = threadIdx.x;
    int w = t >> 5, l = t & 31;
    int grp = l >> 2, qid = l & 3;
    int m0 = blockIdx.x*128;
    int ar  = t & 127;
    int akg = (t >> 7)*16;
    int bk = t >> 3, bn4 = (t & 7)*4;
    float acc[4][4] = {};

    for (int k0 = 0; k0 < K; k0 += 32) {
        #pragma unroll
        for (int i = 0; i < 4; i++) {
            float4 v = *(const float4*)(A + (long long)(m0+ar)*K + k0 + akg + i*4);
            As[akg+i*4+0][ar]=f2tf(v.x); As[akg+i*4+1][ar]=f2tf(v.y);
            As[akg+i*4+2][ar]=f2tf(v.z); As[akg+i*4+3][ar]=f2tf(v.w);
        }
        {
            float4 v = *(const float4*)(B + (long long)(k0+bk)*32 + bn4);
            Bs[bk][bn4+0]=f2tf(v.x); Bs[bk][bn4+1]=f2tf(v.y);
            Bs[bk][bn4+2]=f2tf(v.z); Bs[bk][bn4+3]=f2tf(v.w);
        }
        __syncthreads();
        #pragma unroll
        for (int ks = 0; ks < 4; ks++) {
            int kb = ks*8;
            int mb = w*16;
            unsigned a0 = As[kb+qid  ][mb+grp  ];
            unsigned a1 = As[kb+qid  ][mb+grp+8];
            unsigned a2 = As[kb+qid+4][mb+grp  ];
            unsigned a3 = As[kb+qid+4][mb+grp+8];
            #pragma unroll
            for (int ni = 0; ni < 4; ni++) {
                unsigned b0 = Bs[kb+qid  ][ni*8+grp];
                unsigned b1 = Bs[kb+qid+4][ni*8+grp];
                mma_tf32(acc[ni], a0, a1, a2, a3, b0, b1);
            }
        }
        __syncthreads();
    }
    #pragma unroll
    for (int ni = 0; ni < 4; ni++)
        #pragma unroll
        for (int r = 0; r < 4; r++) {
            int gm = m0 + w*16 + grp + ((r >= 2) ? 8 : 0);
            int gn = ni*8 + 2*qid + (r & 1);
            C[(long long)gm*32 + gn] = acc[ni][r];
        }
}

// ---------------- misc -------------------------------------------------------
__global__ void landmark_kernel(const float* __restrict__ q, const float* __restrict__ k,
                                float* __restrict__ ql, float* __restrict__ kl) {
    long long idx = (long long)blockIdx.x*256 + threadIdx.x;
    int d = idx & 31;
    long long t = idx >> 5;
    int m = (int)(t & (CML-1));
    long long bh = t >> 8;
    long long base = (bh*CN + (long long)m*16)*CDH + d;
    float sq = 0.f, sk = 0.f;
    #pragma unroll
    for (int j = 0; j < 16; j++) { sq += q[base + j*CDH]; sk += k[base + j*CDH]; }
    ql[idx] = sq * 0.0625f;
    kl[idx] = sk * 0.0625f;
}

// per-bh column-sum max -> g_pmax[bh]  (rows of A2 sum to 1, so rowmax==1)
__global__ void abs_colsum_kernel(const float* __restrict__ x) {
    __shared__ float s[256];
    const float* p = x + (long long)blockIdx.x*CML*CML;
    int j = threadIdx.x;
    float sum = 0.f;
    for (int i = 0; i < CML; i++) sum += fabsf(p[i*CML + j]);
    s[j] = sum; __syncthreads();
    for (int o = 128; o > 0; o >>= 1) { if (j < o) s[j] = fmaxf(s[j], s[j+o]); __syncthreads(); }
    if (j == 0) g_pmax[blockIdx.x] = s[0];
}

__global__ void zinit_kernel(const float* __restrict__ x, float* __restrict__ z) {
    __shared__ float dsh;
    if (threadIdx.x < 32) {
        float v = g_pmax[threadIdx.x];
        #pragma unroll
        for (int o = 16; o > 0; o >>= 1) v = fmaxf(v, __shfl_xor_sync(0xffffffffu, v, o));
        if (threadIdx.x == 0) dsh = v;
    }
    __syncthreads();
    float denom = dsh;
    long long idx = (long long)blockIdx.x*256 + threadIdx.x;
    int j = (int)(idx & 255);
    int i = (int)((idx >> 8) & 255);
    long long bh = idx >> 16;
    z[idx] = x[(bh << 16) + ((long long)j << 8) + i] / denom;
}

// fused depthwise conv (k=33) + head merge
__global__ void conv_merge_kernel(const float* __restrict__ oh,
                                  const float* __restrict__ v,
                                  const float* __restrict__ w,
                                  float* __restrict__ out) {
    long long idx = (long long)blockIdx.x*256 + threadIdx.x;
    int d = (int)(idx & 31);
    int h = (int)((idx >> 5) & 7);
    int n = (int)((idx >> 8) & 4095);
    int b = (int)(idx >> 20);
    long long bh = (long long)b*CH + h;
    const float* wp = w + h*33;
    const float* vp = v + bh*(long long)CN*CDH + d;
    float s = 0.f;
    #pragma unroll
    for (int tt = 0; tt < 33; tt++) {
        int nn = n + tt - 16;
        if (nn >= 0 && nn < CN) s = fmaf(vp[(long long)nn*CDH], wp[tt], s);
    }
    out[idx] = oh[(bh*CN + n)*CDH + d] + s;
}

// ---------------- host orchestration -----------------------------------------
extern "C" void kernel_launch(void* const* d_in, const int* in_sizes, int n_in,
                              void* d_out, int out_size) {
    const float* x     = (const float*)d_in[0];
    const float* ln1_g = (const float*)d_in[1];
    const float* ln1_b = (const float*)d_in[2];
    const float* w_qkv = (const float*)d_in[3];
    const float* w_out = (const float*)d_in[4];
    const float* b_out = (const float*)d_in[5];
    const float* res_w = (const float*)d_in[6];
    const float* ln2_g = (const float*)d_in[7];
    const float* ln2_b = (const float*)d_in[8];
    const float* w1    = (const float*)d_in[9];
    const float* b1    = (const float*)d_in[10];
    const float* w2    = (const float*)d_in[11];
    const float* b2    = (const float*)d_in[12];

    float *Y,*XN,*Q,*K,*V,*QL,*KL,*X2,*A2,*Zb,*Z2,*XZ,*T1,*T2,*X1,*P3o,*P3m,*P3l,*OH,*ONBD,*HID;
    unsigned* BAR;
    cudaGetSymbolAddress((void**)&Y,   g_Y);
    cudaGetSymbolAddress((void**)&XN,  g_XN);
    cudaGetSymbolAddress((void**)&Q,   g_Q);
    cudaGetSymbolAddress((void**)&K,   g_K);
    cudaGetSymbolAddress((void**)&V,   g_V);
    cudaGetSymbolAddress((void**)&QL,  g_QL);
    cudaGetSymbolAddress((void**)&KL,  g_KL);
    cudaGetSymbolAddress((void**)&X2,  g_X2);
    cudaGetSymbolAddress((void**)&A2,  g_A2);
    cudaGetSymbolAddress((void**)&Zb,  g_Zb);
    cudaGetSymbolAddress((void**)&Z2,  g_Z2);
    cudaGetSymbolAddress((void**)&XZ,  g_XZ);
    cudaGetSymbolAddress((void**)&T1,  g_T1);
    cudaGetSymbolAddress((void**)&T2,  g_T2);
    cudaGetSymbolAddress((void**)&X1,  g_X1);
    cudaGetSymbolAddress((void**)&P3o, g_P3o);
    cudaGetSymbolAddress((void**)&P3m, g_P3m);
    cudaGetSymbolAddress((void**)&P3l, g_P3l);
    cudaGetSymbolAddress((void**)&OH,  g_OH);
    cudaGetSymbolAddress((void**)&ONBD,g_ONBD);
    cudaGetSymbolAddress((void**)&HID, g_HID);
    cudaGetSymbolAddress((void**)&BAR, g_bar);

    cudaFuncSetAttribute(fused_attn1_kernel,
        cudaFuncAttributeMaxDynamicSharedMemorySize, FUSED_SMEM);
    cudaFuncSetAttribute(fused_attn3_split_kernel,
        cudaFuncAttributeMaxDynamicSharedMemorySize, FUSED_SMEM);

    cudaMemcpyAsync(Y, x, sizeof(float)*(size_t)CB*CN*CD, cudaMemcpyDeviceToDevice);

    const long long MM  = (long long)CML*CML;
    const long long SXD = (long long)CML*CDH;

    for (int blk = 0; blk < 2; blk++) {
        const float* p_ln1g = ln1_g + blk*CD;
        const float* p_ln1b = ln1_b + blk*CD;
        const float* p_wqkv = w_qkv + (long long)blk*CD*3*CINNER;
        const float* p_wout = w_out + (long long)blk*CINNER*CD;
        const float* p_bout = b_out + blk*CD;
        const float* p_resw = res_w + blk*CH*33;
        const float* p_ln2g = ln2_g + blk*CD;
        const float* p_ln2b = ln2_b + blk*CD;
        const float* p_w1   = w1 + (long long)blk*CD*2*CD;
        const float* p_b1   = b1 + blk*2*CD;
        const float* p_w2   = w2 + (long long)blk*2*CD*CD;
        const float* p_b2   = b2 + blk*CD;

        layernorm_kernel<<<CB*CN, 256>>>(Y, p_ln1g, p_ln1b, XN);

        // QKV + fused head-split (Q scaled by dh^-0.5)
        tc_gemm_kernel<6,false><<<dim3(6, 128), 256>>>(XN, p_wqkv, Q, K, V,
            CB*CN, 3*CINNER, CD, 0, 0, 0, 0.f, nullptr, nullptr);

        landmark_kernel<<<(CBH*CML*CDH)/256, 256>>>(Q, K, QL, KL);

        // attn2 = softmax(QL @ KL^T) fused (logits + softmax in one kernel)
        fused_attn2_kernel<<<dim3(2, CBH), 256>>>(QL, KL, A2);

        // pinv init (rowsum max == 1 for softmax rows; only colsum needed)
        abs_colsum_kernel<<<CBH, 256>>>(A2);
        zinit_kernel<<<(int)((CBH*MM)/256), 256>>>(A2, Zb);

        // pinv: 5 bf16 iterations in ONE persistent kernel + 1 tf32 iteration
        cudaMemsetAsync(BAR, 0, sizeof(unsigned));
        pinv_persist_kernel<<<128, 256>>>(A2, Zb, Z2, XZ, T1, T2, 5);
        float* zc = Z2; float* zn = Zb;   // 5 iterations: result lands in Z2
        {
            tc_gemm_kernel<3,false><<<dim3(2,2,CBH), 256>>>(A2, zc, XZ, T1, nullptr,
                CML, CML, CML, MM, MM, MM, 7.0f, nullptr, nullptr);
            tc_gemm_kernel<1,false><<<dim3(2,2,CBH), 256>>>(XZ, T1, T2, nullptr, nullptr,
                CML, CML, CML, MM, MM, MM, 15.0f, nullptr, nullptr);
            tc_gemm_kernel<1,false><<<dim3(2,2,CBH), 256>>>(XZ, T2, T1, nullptr, nullptr,
                CML, CML, CML, MM, MM, MM, 13.0f, nullptr, nullptr);
            tc_gemm_kernel<2,false><<<dim3(2,2,CBH), 256>>>(zc, T1, zn, nullptr, nullptr,
                CML, CML, CML, MM, MM, MM, 0.25f, nullptr, nullptr);
            zc = zn;
        }

        // X1 = softmax(QL @ K^T) @ V  (split over 4 key-chunks + exact merge)
        fused_attn3_split_kernel<<<dim3(2, 4, CBH), 256, FUSED_SMEM>>>(
            QL, K, V, P3o, P3m, P3l);
        attn3_merge_kernel<<<(CBH*CML*CDH)/256, 256>>>(P3o, P3m, P3l, X1);

        // X2 = pinv @ X1
        tc_n32_kernel<<<dim3(2, 1, CBH), 256>>>(zc, X1, X2, CML, CML, MM, SXD, SXD);

        // OH = softmax(Q @ KL^T) @ X2  (fused)
        fused_attn1_kernel<<<dim3(32, CBH), 256, FUSED_SMEM>>>(Q, KL, X2, OH);

        // conv residual + head merge (fused)
        conv_merge_kernel<<<(CB*CN*CD)/256, 256>>>(OH, V, p_resw, ONBD);

        tc_gemm_kernel<4,false><<<dim3(2, 128), 256>>>(ONBD, p_wout, Y, nullptr, nullptr,
            CB*CN, CD, CINNER, 0, 0, 0, 0.f, p_bout, Y);

        layernorm_kernel<<<CB*CN, 256>>>(Y, p_ln2g, p_ln2b, XN);
        tc_gemm_kernel<5,false><<<dim3(4, 128), 256>>>(XN, p_w1, HID, nullptr, nullptr,
            CB*CN, 2*CD, CD, 0, 0, 0, 0.f, p_b1, nullptr);
        tc_gemm_kernel<4,false><<<dim3(2, 128), 256>>>(HID, p_w2, Y, nullptr, nullptr,
            CB*CN, CD, 2*CD, 0, 0, 0, 0.f, p_b2, Y);
    }

    cudaMemcpyAsync(d_out, Y, sizeof(float)*(size_t)CB*CN*CD, cudaMemcpyDeviceToDevice);
}

// round 16
// speedup vs baseline: 1.6560x; 1.6560x over previous
#include <cuda_runtime.h>
#include <math.h>

#define CB 4
#define CN 4096
#define CD 256
#define CH 8
#define CDH 32
#define CML 256
#define CBH (CB*CH)
#define CINNER 256
#define FUSED_SMEM (256*36*4 + 128*40*4)   // 57344 bytes

// ---------------- scratch ----------------------------------------------------
__device__ float g_Y   [CB*CN*CD];
__device__ float g_XN  [CB*CN*CD];
__device__ float g_Q   [CB*CH*CN*CDH];
__device__ float g_K   [CB*CH*CN*CDH];
__device__ float g_V   [CB*CH*CN*CDH];
__device__ float g_QL  [CBH*CML*CDH];
__device__ float g_KL  [CBH*CML*CDH];
__device__ float g_X2  [CBH*CML*CDH];
__device__ float g_A2  [CBH*CML*CML];
__device__ float g_Zb  [CBH*CML*CML];
__device__ float g_Z2  [CBH*CML*CML];
__device__ float g_XZ  [CBH*CML*CML];
__device__ float g_T1  [CBH*CML*CML];
__device__ float g_T2  [CBH*CML*CML];
__device__ float g_X1  [CBH*CML*CDH];
__device__ float g_P3o [4*CBH*CML*CDH];
__device__ float g_P3m [4*CBH*CML];
__device__ float g_P3l [4*CBH*CML];
__device__ float g_OH  [CB*CH*CN*CDH];
__device__ float g_ONBD[CB*CN*CD];
__device__ float g_HID [CB*CN*2*CD];
__device__ float g_gmax2;

__device__ __forceinline__ unsigned f2tf(float x) {
    unsigned u;
    asm("cvt.rna.tf32.f32 %0, %1;" : "=r"(u) : "f"(x));
    return u;
}
__device__ __forceinline__ unsigned pack_bf16(float lo, float hi) {
    unsigned r;
    asm("cvt.rn.bf16x2.f32 %0, %1, %2;" : "=r"(r) : "f"(hi), "f"(lo));
    return r;
}
__device__ __forceinline__ void mma_tf32(float* c, unsigned a0, unsigned a1,
                                         unsigned a2, unsigned a3,
                                         unsigned b0, unsigned b1) {
    asm volatile(
        "mma.sync.aligned.m16n8k8.row.col.f32.tf32.tf32.f32 "
        "{%0,%1,%2,%3}, {%4,%5,%6,%7}, {%8,%9}, {%0,%1,%2,%3};"
        : "+f"(c[0]), "+f"(c[1]), "+f"(c[2]), "+f"(c[3])
        : "r"(a0), "r"(a1), "r"(a2), "r"(a3), "r"(b0), "r"(b1));
}
__device__ __forceinline__ void mma_bf16(float* c, unsigned a0, unsigned a1,
                                         unsigned a2, unsigned a3,
                                         unsigned b0, unsigned b1) {
    asm volatile(
        "mma.sync.aligned.m16n8k16.row.col.f32.bf16.bf16.f32 "
        "{%0,%1,%2,%3}, {%4,%5,%6,%7}, {%8,%9}, {%0,%1,%2,%3};"
        : "+f"(c[0]), "+f"(c[1]), "+f"(c[2]), "+f"(c[3])
        : "r"(a0), "r"(a1), "r"(a2), "r"(a3), "r"(b0), "r"(b1));
}

// ---------------- layernorm --------------------------------------------------
__global__ void layernorm_kernel(const float* __restrict__ x,
                                 const float* __restrict__ g,
                                 const float* __restrict__ b,
                                 float* __restrict__ out) {
    __shared__ float s[256];
    long long row = blockIdx.x;
    int tid = threadIdx.x;
    float v = x[row*CD + tid];
    s[tid] = v; __syncthreads();
    for (int o = 128; o > 0; o >>= 1) { if (tid < o) s[tid] += s[tid+o]; __syncthreads(); }
    float mu = s[0] * (1.0f/CD);
    __syncthreads();
    float d = v - mu;
    s[tid] = d*d; __syncthreads();
    for (int o = 128; o > 0; o >>= 1) { if (tid < o) s[tid] += s[tid+o]; __syncthreads(); }
    float inv = rsqrtf(s[0]*(1.0f/CD) + 1e-5f);
    out[row*CD + tid] = d * inv * g[tid] + b[tid];
}

// ---------------- tf32 TC GEMM 128x128, BK=32 --------------------------------
// EPI: 0 C=AB | 1 aI-AB | 2 a*AB | 3 C=AB,C2=aI-AB | 4 AB+bias+res
//      5 gelu(AB+bias) | 6 qkv-split
template<int EPI, bool TB>
__global__ void __launch_bounds__(256) tc_gemm_kernel(
    const float* __restrict__ A, const float* __restrict__ B,
    float* __restrict__ C, float* __restrict__ C2, float* __restrict__ C3,
    int M, int N, int K,
    long long sA, long long sB, long long sC,
    float alpha, const float* __restrict__ bias, const float* __restrict__ res)
{
    A += (long long)blockIdx.z * sA;
    B += (long long)blockIdx.z * sB;
    C += (long long)blockIdx.z * sC;
    if (EPI == 3) C2 += (long long)blockIdx.z * sC;

    int m0 = blockIdx.y*128, n0 = blockIdx.x*128;
    __shared__ unsigned As[32][132];
    __shared__ unsigned Bs[32][132];
    int t = threadIdx.x;
    int w = t >> 5, l = t & 31;
    int wm = (w >> 2)*64, wn = (w & 3)*32;
    int grp = l >> 2, qid = l & 3;
    float acc[4][4][4] = {};
    int ar  = t & 127;
    int akg = (t >> 7)*16;
    int bkr = t >> 3;
    int bn4 = (t & 7)*4;

    const float* Arow = A + (long long)(m0+ar)*K;
    const float* Brow = TB ? (B + (long long)(n0+ar)*K) : nullptr;

    float4 pa[4], pb[4];
    #pragma unroll
    for (int i = 0; i < 4; i++) pa[i] = *(const float4*)(Arow + akg + i*4);
    if (!TB) {
        #pragma unroll
        for (int i = 0; i < 4; i++)
            pb[i] = *(const float4*)(B + (long long)bkr*N + n0 + bn4 + i*32);
    } else {
        #pragma unroll
        for (int i = 0; i < 4; i++) pb[i] = *(const float4*)(Brow + akg + i*4);
    }

    for (int k0 = 0; k0 < K; k0 += 32) {
        #pragma unroll
        for (int i = 0; i < 4; i++) {
            As[akg+i*4+0][ar]=f2tf(pa[i].x); As[akg+i*4+1][ar]=f2tf(pa[i].y);
            As[akg+i*4+2][ar]=f2tf(pa[i].z); As[akg+i*4+3][ar]=f2tf(pa[i].w);
        }
        if (!TB) {
            #pragma unroll
            for (int i = 0; i < 4; i++) {
                int n = bn4 + i*32;
                Bs[bkr][n+0]=f2tf(pb[i].x); Bs[bkr][n+1]=f2tf(pb[i].y);
                Bs[bkr][n+2]=f2tf(pb[i].z); Bs[bkr][n+3]=f2tf(pb[i].w);
            }
        } else {
            #pragma unroll
            for (int i = 0; i < 4; i++) {
                Bs[akg+i*4+0][ar]=f2tf(pb[i].x); Bs[akg+i*4+1][ar]=f2tf(pb[i].y);
                Bs[akg+i*4+2][ar]=f2tf(pb[i].z); Bs[akg+i*4+3][ar]=f2tf(pb[i].w);
            }
        }
        __syncthreads();
        if (k0 + 32 < K) {
            int kn = k0 + 32;
            #pragma unroll
            for (int i = 0; i < 4; i++) pa[i] = *(const float4*)(Arow + kn + akg + i*4);
            if (!TB) {
                #pragma unroll
                for (int i = 0; i < 4; i++)
                    pb[i] = *(const float4*)(B + (long long)(kn+bkr)*N + n0 + bn4 + i*32);
            } else {
                #pragma unroll
                for (int i = 0; i < 4; i++) pb[i] = *(const float4*)(Brow + kn + akg + i*4);
            }
        }
        #pragma unroll
        for (int ks = 0; ks < 4; ks++) {
            int kb = ks*8;
            unsigned af[4][4], bf[4][2];
            #pragma unroll
            for (int mi = 0; mi < 4; mi++) {
                int mb = wm + mi*16;
                af[mi][0] = As[kb+qid  ][mb+grp  ];
                af[mi][1] = As[kb+qid  ][mb+grp+8];
                af[mi][2] = As[kb+qid+4][mb+grp  ];
                af[mi][3] = As[kb+qid+4][mb+grp+8];
            }
            #pragma unroll
            for (int ni = 0; ni < 4; ni++) {
                int nb = wn + ni*8;
                bf[ni][0] = Bs[kb+qid  ][nb+grp];
                bf[ni][1] = Bs[kb+qid+4][nb+grp];
            }
            #pragma unroll
            for (int mi = 0; mi < 4; mi++)
                #pragma unroll
                for (int ni = 0; ni < 4; ni++)
                    mma_tf32(acc[mi][ni], af[mi][0], af[mi][1], af[mi][2], af[mi][3],
                             bf[ni][0], bf[ni][1]);
        }
        __syncthreads();
    }
    #pragma unroll
    for (int mi = 0; mi < 4; mi++)
        #pragma unroll
        for (int ni = 0; ni < 4; ni++)
            #pragma unroll
            for (int r = 0; r < 4; r++) {
                int gm = m0 + wm + mi*16 + grp + ((r >= 2) ? 8 : 0);
                int gn = n0 + wn + ni*8 + 2*qid + (r & 1);
                float v = acc[mi][ni][r];
                long long off = (long long)gm*N + gn;
                if (EPI == 6) {
                    int which = gn >> 8;
                    int h = (gn >> 5) & 7;
                    int d = gn & 31;
                    int b = gm >> 12;
                    int n_tok = gm & 4095;
                    long long dst = ((((long long)b*CH + h)*CN) + n_tok)*CDH + d;
                    if (which == 0)      C [dst] = v * 0.17677669529663687f;
                    else if (which == 1) C2[dst] = v;
                    else                 C3[dst] = v;
                    continue;
                }
                if (EPI == 1)      C[off] = ((gm==gn)?alpha:0.0f) - v;
                else if (EPI == 2) C[off] = alpha * v;
                else if (EPI == 4) C[off] = v + bias[gn] + res[off];
                else if (EPI == 5) { v += bias[gn]; C[off] = 0.5f*v*(1.0f + erff(v*0.70710678118654752f)); }
                else               C[off] = v;
                if (EPI == 3)      C2[off] = ((gm==gn)?alpha:0.0f) - v;
            }
}

// ---------------- bf16 TC GEMM 128x128, BK=32 (pinv iterations) --------------
// Non-transposed B only. EPI: 1 aI-AB | 2 a*AB | 3 C=AB,C2=aI-AB
template<int EPI>
__global__ void __launch_bounds__(256) bf_gemm_kernel(
    const float* __restrict__ A, const float* __restrict__ B,
    float* __restrict__ C, float* __restrict__ C2,
    int N, int K, long long sAB, float alpha)
{
    A += (long long)blockIdx.z * sAB;
    B += (long long)blockIdx.z * sAB;
    C += (long long)blockIdx.z * sAB;
    if (EPI == 3) C2 += (long long)blockIdx.z * sAB;

    int m0 = blockIdx.y*128, n0 = blockIdx.x*128;
    __shared__ unsigned As[16][132];
    __shared__ unsigned Bs[16][132];
    int t = threadIdx.x;
    int w = t >> 5, l = t & 31;
    int wm = (w >> 2)*64, wn = (w & 3)*32;
    int grp = l >> 2, qid = l & 3;
    float acc[4][4][4] = {};
    int ar  = t & 127;
    int akg = (t >> 7)*16;
    int bpr = t >> 4;
    int bn8 = (t & 15)*8;

    const float* Arow = A + (long long)(m0+ar)*K;

    float4 pa[4], pb0a, pb0b, pb1a, pb1b;
    #pragma unroll
    for (int i = 0; i < 4; i++) pa[i] = *(const float4*)(Arow + akg + i*4);
    {
        const float* b0 = B + (long long)(2*bpr  )*N + n0 + bn8;
        const float* b1 = B + (long long)(2*bpr+1)*N + n0 + bn8;
        pb0a = *(const float4*)b0; pb0b = *(const float4*)(b0+4);
        pb1a = *(const float4*)b1; pb1b = *(const float4*)(b1+4);
    }

    for (int k0 = 0; k0 < K; k0 += 32) {
        int ap = akg >> 1;
        #pragma unroll
        for (int i = 0; i < 4; i++) {
            As[ap+2*i  ][ar] = pack_bf16(pa[i].x, pa[i].y);
            As[ap+2*i+1][ar] = pack_bf16(pa[i].z, pa[i].w);
        }
        Bs[bpr][bn8+0] = pack_bf16(pb0a.x, pb1a.x);
        Bs[bpr][bn8+1] = pack_bf16(pb0a.y, pb1a.y);
        Bs[bpr][bn8+2] = pack_bf16(pb0a.z, pb1a.z);
        Bs[bpr][bn8+3] = pack_bf16(pb0a.w, pb1a.w);
        Bs[bpr][bn8+4] = pack_bf16(pb0b.x, pb1b.x);
        Bs[bpr][bn8+5] = pack_bf16(pb0b.y, pb1b.y);
        Bs[bpr][bn8+6] = pack_bf16(pb0b.z, pb1b.z);
        Bs[bpr][bn8+7] = pack_bf16(pb0b.w, pb1b.w);
        __syncthreads();
        if (k0 + 32 < K) {
            int kn = k0 + 32;
            #pragma unroll
            for (int i = 0; i < 4; i++) pa[i] = *(const float4*)(Arow + kn + akg + i*4);
            const float* b0 = B + (long long)(kn + 2*bpr  )*N + n0 + bn8;
            const float* b1 = B + (long long)(kn + 2*bpr+1)*N + n0 + bn8;
            pb0a = *(const float4*)b0; pb0b = *(const float4*)(b0+4);
            pb1a = *(const float4*)b1; pb1b = *(const float4*)(b1+4);
        }
        #pragma unroll
        for (int kc = 0; kc < 2; kc++) {
            int p0 = kc*8;
            unsigned af[4][4], bf[4][2];
            #pragma unroll
            for (int mi = 0; mi < 4; mi++) {
                int mb = wm + mi*16;
                af[mi][0] = As[p0+qid  ][mb+grp  ];
                af[mi][1] = As[p0+qid  ][mb+grp+8];
                af[mi][2] = As[p0+qid+4][mb+grp  ];
                af[mi][3] = As[p0+qid+4][mb+grp+8];
            }
            #pragma unroll
            for (int ni = 0; ni < 4; ni++) {
                int nb = wn + ni*8;
                bf[ni][0] = Bs[p0+qid  ][nb+grp];
                bf[ni][1] = Bs[p0+qid+4][nb+grp];
            }
            #pragma unroll
            for (int mi = 0; mi < 4; mi++)
                #pragma unroll
                for (int ni = 0; ni < 4; ni++)
                    mma_bf16(acc[mi][ni], af[mi][0], af[mi][1], af[mi][2], af[mi][3],
                             bf[ni][0], bf[ni][1]);
        }
        __syncthreads();
    }
    #pragma unroll
    for (int mi = 0; mi < 4; mi++)
        #pragma unroll
        for (int ni = 0; ni < 4; ni++)
            #pragma unroll
            for (int r = 0; r < 4; r++) {
                int gm = m0 + wm + mi*16 + grp + ((r >= 2) ? 8 : 0);
                int gn = n0 + wn + ni*8 + 2*qid + (r & 1);
                float v = acc[mi][ni][r];
                long long off = (long long)gm*N + gn;
                if (EPI == 1)      C[off] = ((gm==gn)?alpha:0.0f) - v;
                else if (EPI == 2) C[off] = alpha * v;
                else               C[off] = v;
                if (EPI == 3)      C2[off] = ((gm==gn)?alpha:0.0f) - v;
            }
}

// ---------------- fused attn1: OH = softmax(Q @ KL^T) @ X2 -------------------
__global__ void __launch_bounds__(256) fused_attn1_kernel(
    const float* __restrict__ Q, const float* __restrict__ KL,
    const float* __restrict__ X2, float* __restrict__ OH)
{
    extern __shared__ unsigned smemu[];
    unsigned (*sKL)[36]  = (unsigned(*)[36])smemu;
    unsigned (*sX2p)[40] = (unsigned(*)[40])(smemu + 256*36);
    int bh = blockIdx.y;
    int m0 = blockIdx.x * 128;
    int t = threadIdx.x;
    int w = t >> 5, l = t & 31;
    int grp = l >> 2, qid = l & 3;
    const float* Qp  = Q  + ((long long)bh*CN + m0)*CDH;
    const float* KLp = KL + (long long)bh*CML*CDH;
    const float* Xp  = X2 + (long long)bh*CML*CDH;

    #pragma unroll
    for (int i = 0; i < 8; i++) {
        int e = t + i*256;
        int n = e >> 3, kq = (e & 7)*4;
        float4 v = *(const float4*)(KLp + n*32 + kq);
        sKL[n][kq+0]=f2tf(v.x); sKL[n][kq+1]=f2tf(v.y);
        sKL[n][kq+2]=f2tf(v.z); sKL[n][kq+3]=f2tf(v.w);
    }
    #pragma unroll
    for (int i = 0; i < 4; i++) {
        int e = t + i*256;
        int kh = e >> 3, nq = (e & 7)*4;
        float4 v0 = *(const float4*)(Xp + (2*kh  )*32 + nq);
        float4 v1 = *(const float4*)(Xp + (2*kh+1)*32 + nq);
        sX2p[kh][nq+0] = pack_bf16(v0.x, v1.x);
        sX2p[kh][nq+1] = pack_bf16(v0.y, v1.y);
        sX2p[kh][nq+2] = pack_bf16(v0.z, v1.z);
        sX2p[kh][nq+3] = pack_bf16(v0.w, v1.w);
    }
    __syncthreads();

    int mr = w*16;
    unsigned aq[4][4];
    #pragma unroll
    for (int ks = 0; ks < 4; ks++) {
        int k = ks*8;
        aq[ks][0] = f2tf(Qp[(mr+grp  )*32 + k+qid  ]);
        aq[ks][1] = f2tf(Qp[(mr+grp+8)*32 + k+qid  ]);
        aq[ks][2] = f2tf(Qp[(mr+grp  )*32 + k+qid+4]);
        aq[ks][3] = f2tf(Qp[(mr+grp+8)*32 + k+qid+4]);
    }
    float acc[32][4];
    #pragma unroll
    for (int ni = 0; ni < 32; ni++) { acc[ni][0]=0.f; acc[ni][1]=0.f; acc[ni][2]=0.f; acc[ni][3]=0.f; }
    #pragma unroll
    for (int ni = 0; ni < 32; ni++)
        #pragma unroll
        for (int ks = 0; ks < 4; ks++) {
            unsigned b0 = sKL[ni*8+grp][ks*8+qid];
            unsigned b1 = sKL[ni*8+grp][ks*8+qid+4];
            mma_tf32(acc[ni], aq[ks][0], aq[ks][1], aq[ks][2], aq[ks][3], b0, b1);
        }
    float m1 = -3.4e38f, m2 = -3.4e38f;
    #pragma unroll
    for (int ni = 0; ni < 32; ni++) {
        m1 = fmaxf(m1, fmaxf(acc[ni][0], acc[ni][1]));
        m2 = fmaxf(m2, fmaxf(acc[ni][2], acc[ni][3]));
    }
    m1 = fmaxf(m1, __shfl_xor_sync(0xffffffffu, m1, 1));
    m1 = fmaxf(m1, __shfl_xor_sync(0xffffffffu, m1, 2));
    m2 = fmaxf(m2, __shfl_xor_sync(0xffffffffu, m2, 1));
    m2 = fmaxf(m2, __shfl_xor_sync(0xffffffffu, m2, 2));
    float s1 = 0.f, s2 = 0.f;
    #pragma unroll
    for (int ni = 0; ni < 32; ni++) {
        acc[ni][0] = __expf(acc[ni][0]-m1); acc[ni][1] = __expf(acc[ni][1]-m1);
        acc[ni][2] = __expf(acc[ni][2]-m2); acc[ni][3] = __expf(acc[ni][3]-m2);
        s1 += acc[ni][0] + acc[ni][1];
        s2 += acc[ni][2] + acc[ni][3];
    }
    s1 += __shfl_xor_sync(0xffffffffu, s1, 1);
    s1 += __shfl_xor_sync(0xffffffffu, s1, 2);
    s2 += __shfl_xor_sync(0xffffffffu, s2, 1);
    s2 += __shfl_xor_sync(0xffffffffu, s2, 2);
    float i1 = 1.0f/s1, i2 = 1.0f/s2;
    #pragma unroll
    for (int ni = 0; ni < 32; ni++) {
        acc[ni][0]*=i1; acc[ni][1]*=i1; acc[ni][2]*=i2; acc[ni][3]*=i2;
    }
    float ao[4][4] = {};
    #pragma unroll
    for (int c = 0; c < 16; c++) {
        unsigned a0 = pack_bf16(acc[2*c  ][0], acc[2*c  ][1]);
        unsigned a1 = pack_bf16(acc[2*c  ][2], acc[2*c  ][3]);
        unsigned a2 = pack_bf16(acc[2*c+1][0], acc[2*c+1][1]);
        unsigned a3 = pack_bf16(acc[2*c+1][2], acc[2*c+1][3]);
        #pragma unroll
        for (int j = 0; j < 4; j++) {
            unsigned b0 = sX2p[c*8+qid  ][j*8+grp];
            unsigned b1 = sX2p[c*8+qid+4][j*8+grp];
            mma_bf16(ao[j], a0, a1, a2, a3, b0, b1);
        }
    }
    float* Op = OH + ((long long)bh*CN + m0 + mr)*CDH;
    #pragma unroll
    for (int j = 0; j < 4; j++) {
        Op[(grp  )*32 + j*8+2*qid  ] = ao[j][0];
        Op[(grp  )*32 + j*8+2*qid+1] = ao[j][1];
        Op[(grp+8)*32 + j*8+2*qid  ] = ao[j][2];
        Op[(grp+8)*32 + j*8+2*qid+1] = ao[j][3];
    }
}

// ---------------- fused attn3 split over 4 key-chunks ------------------------
__global__ void __launch_bounds__(256) fused_attn3_split_kernel(
    const float* __restrict__ QL, const float* __restrict__ Kg,
    const float* __restrict__ V,
    float* __restrict__ po, float* __restrict__ pm, float* __restrict__ pl)
{
    extern __shared__ unsigned smemu[];
    unsigned (*sK)[36]  = (unsigned(*)[36])smemu;
    unsigned (*sVp)[40] = (unsigned(*)[40])(smemu + 256*36);
    int bh = blockIdx.z;
    int chunk = blockIdx.y;
    int m0 = blockIdx.x * 128;
    int t = threadIdx.x;
    int w = t >> 5, l = t & 31;
    int grp = l >> 2, qid = l & 3;
    const float* Qp = QL + ((long long)bh*CML + m0)*CDH;

    int mr = w*16;
    unsigned aq[4][4];
    #pragma unroll
    for (int ks = 0; ks < 4; ks++) {
        int k = ks*8;
        aq[ks][0] = f2tf(Qp[(mr+grp  )*32 + k+qid  ]);
        aq[ks][1] = f2tf(Qp[(mr+grp+8)*32 + k+qid  ]);
        aq[ks][2] = f2tf(Qp[(mr+grp  )*32 + k+qid+4]);
        aq[ks][3] = f2tf(Qp[(mr+grp+8)*32 + k+qid+4]);
    }
    float ao[4][4] = {};
    float m1 = -3.4e38f, m2 = -3.4e38f, l1 = 0.f, l2 = 0.f;

    for (int kc = chunk*4; kc < chunk*4 + 4; kc++) {
        __syncthreads();
        const float* Kp = Kg + ((long long)bh*CN + kc*256)*CDH;
        const float* Vp = V  + ((long long)bh*CN + kc*256)*CDH;
        #pragma unroll
        for (int i = 0; i < 8; i++) {
            int e = t + i*256;
            int n = e >> 3, kq = (e & 7)*4;
            float4 v = *(const float4*)(Kp + n*32 + kq);
            sK[n][kq+0]=f2tf(v.x); sK[n][kq+1]=f2tf(v.y);
            sK[n][kq+2]=f2tf(v.z); sK[n][kq+3]=f2tf(v.w);
        }
        #pragma unroll
        for (int i = 0; i < 4; i++) {
            int e = t + i*256;
            int kh = e >> 3, nq = (e & 7)*4;
            float4 v0 = *(const float4*)(Vp + (2*kh  )*32 + nq);
            float4 v1 = *(const float4*)(Vp + (2*kh+1)*32 + nq);
            sVp[kh][nq+0] = pack_bf16(v0.x, v1.x);
            sVp[kh][nq+1] = pack_bf16(v0.y, v1.y);
            sVp[kh][nq+2] = pack_bf16(v0.z, v1.z);
            sVp[kh][nq+3] = pack_bf16(v0.w, v1.w);
        }
        __syncthreads();
        float acc[32][4];
        #pragma unroll
        for (int ni = 0; ni < 32; ni++) { acc[ni][0]=0.f; acc[ni][1]=0.f; acc[ni][2]=0.f; acc[ni][3]=0.f; }
        #pragma unroll
        for (int ni = 0; ni < 32; ni++)
            #pragma unroll
            for (int ks = 0; ks < 4; ks++) {
                unsigned b0 = sK[ni*8+grp][ks*8+qid];
                unsigned b1 = sK[ni*8+grp][ks*8+qid+4];
                mma_tf32(acc[ni], aq[ks][0], aq[ks][1], aq[ks][2], aq[ks][3], b0, b1);
            }
        float c1 = -3.4e38f, c2 = -3.4e38f;
        #pragma unroll
        for (int ni = 0; ni < 32; ni++) {
            c1 = fmaxf(c1, fmaxf(acc[ni][0], acc[ni][1]));
            c2 = fmaxf(c2, fmaxf(acc[ni][2], acc[ni][3]));
        }
        c1 = fmaxf(c1, __shfl_xor_sync(0xffffffffu, c1, 1));
        c1 = fmaxf(c1, __shfl_xor_sync(0xffffffffu, c1, 2));
        c2 = fmaxf(c2, __shfl_xor_sync(0xffffffffu, c2, 1));
        c2 = fmaxf(c2, __shfl_xor_sync(0xffffffffu, c2, 2));
        float n1 = fmaxf(m1, c1), n2 = fmaxf(m2, c2);
        float sc1 = __expf(m1 - n1), sc2 = __expf(m2 - n2);
        float s1 = 0.f, s2 = 0.f;
        #pragma unroll
        for (int ni = 0; ni < 32; ni++) {
            acc[ni][0] = __expf(acc[ni][0]-n1); acc[ni][1] = __expf(acc[ni][1]-n1);
            acc[ni][2] = __expf(acc[ni][2]-n2); acc[ni][3] = __expf(acc[ni][3]-n2);
            s1 += acc[ni][0] + acc[ni][1];
            s2 += acc[ni][2] + acc[ni][3];
        }
        s1 += __shfl_xor_sync(0xffffffffu, s1, 1);
        s1 += __shfl_xor_sync(0xffffffffu, s1, 2);
        s2 += __shfl_xor_sync(0xffffffffu, s2, 1);
        s2 += __shfl_xor_sync(0xffffffffu, s2, 2);
        l1 = l1*sc1 + s1; l2 = l2*sc2 + s2;
        m1 = n1; m2 = n2;
        #pragma unroll
        for (int j = 0; j < 4; j++) {
            ao[j][0]*=sc1; ao[j][1]*=sc1; ao[j][2]*=sc2; ao[j][3]*=sc2;
        }
        #pragma unroll
        for (int c = 0; c < 16; c++) {
            unsigned a0 = pack_bf16(acc[2*c  ][0], acc[2*c  ][1]);
            unsigned a1 = pack_bf16(acc[2*c  ][2], acc[2*c  ][3]);
            unsigned a2 = pack_bf16(acc[2*c+1][0], acc[2*c+1][1]);
            unsigned a3 = pack_bf16(acc[2*c+1][2], acc[2*c+1][3]);
            #pragma unroll
            for (int j = 0; j < 4; j++) {
                unsigned b0 = sVp[c*8+qid  ][j*8+grp];
                unsigned b1 = sVp[c*8+qid+4][j*8+grp];
                mma_bf16(ao[j], a0, a1, a2, a3, b0, b1);
            }
        }
    }
    int r1 = m0 + mr + grp, r2 = r1 + 8;
    long long sb = ((long long)chunk*CBH + bh)*CML;
    float* Op  = po + (sb + r1)*CDH;
    float* Op2 = po + (sb + r2)*CDH;
    #pragma unroll
    for (int j = 0; j < 4; j++) {
        Op [j*8+2*qid  ] = ao[j][0];
        Op [j*8+2*qid+1] = ao[j][1];
        Op2[j*8+2*qid  ] = ao[j][2];
        Op2[j*8+2*qid+1] = ao[j][3];
    }
    if (qid == 0) {
        pm[sb + r1] = m1; pl[sb + r1] = l1;
        pm[sb + r2] = m2; pl[sb + r2] = l2;
    }
}

// merge 4 chunk partials -> X1
__global__ void attn3_merge_kernel(
    const float* __restrict__ po, const float* __restrict__ pm,
    const float* __restrict__ pl, float* __restrict__ X1)
{
    long long idx = (long long)blockIdx.x*256 + threadIdx.x;
    int d = (int)(idx & 31);
    int r = (int)((idx >> 5) & 255);
    int bh = (int)(idx >> 13);
    float m = -3.4e38f;
    #pragma unroll
    for (int c = 0; c < 4; c++)
        m = fmaxf(m, pm[((long long)c*CBH + bh)*CML + r]);
    float l = 0.f, o = 0.f;
    #pragma unroll
    for (int c = 0; c < 4; c++) {
        long long s = ((long long)c*CBH + bh)*CML + r;
        float e = __expf(pm[s] - m);
        l += pl[s] * e;
        o += po[s*CDH + d] * e;
    }
    X1[idx] = o / l;
}

// ---------------- narrow-N (N=32) tf32 TC GEMM -------------------------------
__global__ void __launch_bounds__(256) tc_n32_kernel(
    const float* __restrict__ A, const float* __restrict__ B, float* __restrict__ C,
    int M, int K, long long sA, long long sB, long long sC)
{
    A += (long long)blockIdx.z * sA;
    B += (long long)blockIdx.z * sB;
    C += (long long)blockIdx.z * sC;
    __shared__ unsigned As[32][132];
    __shared__ unsigned Bs[32][36];
    int t = threadIdx.x;
    int w = t >> 5, l = t & 31;
    int grp = l >> 2, qid = l & 3;
    int m0 = blockIdx.x*128;
    int ar  = t & 127;
    int akg = (t >> 7)*16;
    int bk = t >> 3, bn4 = (t & 7)*4;
    float acc[4][4] = {};

    for (int k0 = 0; k0 < K; k0 += 32) {
        #pragma unroll
        for (int i = 0; i < 4; i++) {
            float4 v = *(const float4*)(A + (long long)(m0+ar)*K + k0 + akg + i*4);
            As[akg+i*4+0][ar]=f2tf(v.x); As[akg+i*4+1][ar]=f2tf(v.y);
            As[akg+i*4+2][ar]=f2tf(v.z); As[akg+i*4+3][ar]=f2tf(v.w);
        }
        {
            float4 v = *(const float4*)(B + (long long)(k0+bk)*32 + bn4);
            Bs[bk][bn4+0]=f2tf(v.x); Bs[bk][bn4+1]=f2tf(v.y);
            Bs[bk][bn4+2]=f2tf(v.z); Bs[bk][bn4+3]=f2tf(v.w);
        }
        __syncthreads();
        #pragma unroll
        for (int ks = 0; ks < 4; ks++) {
            int kb = ks*8;
            int mb = w*16;
            unsigned a0 = As[kb+qid  ][mb+grp  ];
            unsigned a1 = As[kb+qid  ][mb+grp+8];
            unsigned a2 = As[kb+qid+4][mb+grp  ];
            unsigned a3 = As[kb+qid+4][mb+grp+8];
            #pragma unroll
            for (int ni = 0; ni < 4; ni++) {
                unsigned b0 = Bs[kb+qid  ][ni*8+grp];
                unsigned b1 = Bs[kb+qid+4][ni*8+grp];
                mma_tf32(acc[ni], a0, a1, a2, a3, b0, b1);
            }
        }
        __syncthreads();
    }
    #pragma unroll
    for (int ni = 0; ni < 4; ni++)
        #pragma unroll
        for (int r = 0; r < 4; r++) {
            int gm = m0 + w*16 + grp + ((r >= 2) ? 8 : 0);
            int gn = ni*8 + 2*qid + (r & 1);
            C[(long long)gm*32 + gn] = acc[ni][r];
        }
}

// ---------------- softmax 256 ------------------------------------------------
__global__ void softmax256_kernel(float* __restrict__ x) {
    long long row = (long long)blockIdx.x*8 + (threadIdx.x >> 5);
    int lane = threadIdx.x & 31;
    float* p = x + row*256;
    float4 a = *(float4*)(p + lane*4);
    float4 b = *(float4*)(p + 128 + lane*4);
    float m = fmaxf(fmaxf(fmaxf(a.x,a.y), fmaxf(a.z,a.w)),
                    fmaxf(fmaxf(b.x,b.y), fmaxf(b.z,b.w)));
    #pragma unroll
    for (int o = 16; o > 0; o >>= 1) m = fmaxf(m, __shfl_xor_sync(0xffffffffu, m, o));
    a.x=__expf(a.x-m); a.y=__expf(a.y-m); a.z=__expf(a.z-m); a.w=__expf(a.w-m);
    b.x=__expf(b.x-m); b.y=__expf(b.y-m); b.z=__expf(b.z-m); b.w=__expf(b.w-m);
    float s = a.x+a.y+a.z+a.w + b.x+b.y+b.z+b.w;
    #pragma unroll
    for (int o = 16; o > 0; o >>= 1) s += __shfl_xor_sync(0xffffffffu, s, o);
    float inv = 1.0f / s;
    a.x*=inv; a.y*=inv; a.z*=inv; a.w*=inv;
    b.x*=inv; b.y*=inv; b.z*=inv; b.w*=inv;
    *(float4*)(p + lane*4) = a;
    *(float4*)(p + 128 + lane*4) = b;
}

// ---------------- misc -------------------------------------------------------
__global__ void landmark_kernel(const float* __restrict__ q, const float* __restrict__ k,
                                float* __restrict__ ql, float* __restrict__ kl) {
    long long idx = (long long)blockIdx.x*256 + threadIdx.x;
    int d = idx & 31;
    long long t = idx >> 5;
    int m = (int)(t & (CML-1));
    long long bh = t >> 8;
    long long base = (bh*CN + (long long)m*16)*CDH + d;
    float sq = 0.f, sk = 0.f;
    #pragma unroll
    for (int j = 0; j < 16; j++) { sq += q[base + j*CDH]; sk += k[base + j*CDH]; }
    ql[idx] = sq * 0.0625f;
    kl[idx] = sk * 0.0625f;
}

// colsum max (rows of A2 sum to 1 exactly -> rowsum max == 1; only colsum needed)
__global__ void abs_colsum_max_kernel(const float* __restrict__ x) {
    const float* p = x + (long long)blockIdx.x*CML*CML;
    int j = threadIdx.x;
    float s = 0.f;
    for (int i = 0; i < CML; i++) s += fabsf(p[i*CML + j]);
    atomicMax((int*)&g_gmax2, __float_as_int(s));
}

__global__ void zinit_kernel(const float* __restrict__ x, float* __restrict__ z) {
    long long idx = (long long)blockIdx.x*256 + threadIdx.x;
    int j = (int)(idx & 255);
    int i = (int)((idx >> 8) & 255);
    long long bh = idx >> 16;
    float denom = g_gmax2;
    z[idx] = x[(bh << 16) + ((long long)j << 8) + i] / denom;
}

// fused depthwise conv (k=33) + head merge
__global__ void conv_merge_kernel(const float* __restrict__ oh,
                                  const float* __restrict__ v,
                                  const float* __restrict__ w,
                                  float* __restrict__ out) {
    long long idx = (long long)blockIdx.x*256 + threadIdx.x;
    int d = (int)(idx & 31);
    int h = (int)((idx >> 5) & 7);
    int n = (int)((idx >> 8) & 4095);
    int b = (int)(idx >> 20);
    long long bh = (long long)b*CH + h;
    const float* wp = w + h*33;
    const float* vp = v + bh*(long long)CN*CDH + d;
    float s = 0.f;
    #pragma unroll
    for (int tt = 0; tt < 33; tt++) {
        int nn = n + tt - 16;
        if (nn >= 0 && nn < CN) s = fmaf(vp[(long long)nn*CDH], wp[tt], s);
    }
    out[idx] = oh[(bh*CN + n)*CDH + d] + s;
}

// ---------------- host orchestration -----------------------------------------
extern "C" void kernel_launch(void* const* d_in, const int* in_sizes, int n_in,
                              void* d_out, int out_size) {
    const float* x     = (const float*)d_in[0];
    const float* ln1_g = (const float*)d_in[1];
    const float* ln1_b = (const float*)d_in[2];
    const float* w_qkv = (const float*)d_in[3];
    const float* w_out = (const float*)d_in[4];
    const float* b_out = (const float*)d_in[5];
    const float* res_w = (const float*)d_in[6];
    const float* ln2_g = (const float*)d_in[7];
    const float* ln2_b = (const float*)d_in[8];
    const float* w1    = (const float*)d_in[9];
    const float* b1    = (const float*)d_in[10];
    const float* w2    = (const float*)d_in[11];
    const float* b2    = (const float*)d_in[12];

    float *Y,*XN,*Q,*K,*V,*QL,*KL,*X2,*A2,*Zb,*Z2,*XZ,*T1,*T2,*X1,*P3o,*P3m,*P3l,*OH,*ONBD,*HID,*G2;
    cudaGetSymbolAddress((void**)&Y,   g_Y);
    cudaGetSymbolAddress((void**)&XN,  g_XN);
    cudaGetSymbolAddress((void**)&Q,   g_Q);
    cudaGetSymbolAddress((void**)&K,   g_K);
    cudaGetSymbolAddress((void**)&V,   g_V);
    cudaGetSymbolAddress((void**)&QL,  g_QL);
    cudaGetSymbolAddress((void**)&KL,  g_KL);
    cudaGetSymbolAddress((void**)&X2,  g_X2);
    cudaGetSymbolAddress((void**)&A2,  g_A2);
    cudaGetSymbolAddress((void**)&Zb,  g_Zb);
    cudaGetSymbolAddress((void**)&Z2,  g_Z2);
    cudaGetSymbolAddress((void**)&XZ,  g_XZ);
    cudaGetSymbolAddress((void**)&T1,  g_T1);
    cudaGetSymbolAddress((void**)&T2,  g_T2);
    cudaGetSymbolAddress((void**)&X1,  g_X1);
    cudaGetSymbolAddress((void**)&P3o, g_P3o);
    cudaGetSymbolAddress((void**)&P3m, g_P3m);
    cudaGetSymbolAddress((void**)&P3l, g_P3l);
    cudaGetSymbolAddress((void**)&OH,  g_OH);
    cudaGetSymbolAddress((void**)&ONBD,g_ONBD);
    cudaGetSymbolAddress((void**)&HID, g_HID);
    cudaGetSymbolAddress((void**)&G2,  g_gmax2);

    cudaFuncSetAttribute(fused_attn1_kernel,
        cudaFuncAttributeMaxDynamicSharedMemorySize, FUSED_SMEM);
    cudaFuncSetAttribute(fused_attn3_split_kernel,
        cudaFuncAttributeMaxDynamicSharedMemorySize, FUSED_SMEM);

    cudaMemcpyAsync(Y, x, sizeof(float)*(size_t)CB*CN*CD, cudaMemcpyDeviceToDevice);

    const long long MM  = (long long)CML*CML;
    const long long SXD = (long long)CML*CDH;

    for (int blk = 0; blk < 2; blk++) {
        const float* p_ln1g = ln1_g + blk*CD;
        const float* p_ln1b = ln1_b + blk*CD;
        const float* p_wqkv = w_qkv + (long long)blk*CD*3*CINNER;
        const float* p_wout = w_out + (long long)blk*CINNER*CD;
        const float* p_bout = b_out + blk*CD;
        const float* p_resw = res_w + blk*CH*33;
        const float* p_ln2g = ln2_g + blk*CD;
        const float* p_ln2b = ln2_b + blk*CD;
        const float* p_w1   = w1 + (long long)blk*CD*2*CD;
        const float* p_b1   = b1 + blk*2*CD;
        const float* p_w2   = w2 + (long long)blk*2*CD*CD;
        const float* p_b2   = b2 + blk*CD;

        layernorm_kernel<<<CB*CN, 256>>>(Y, p_ln1g, p_ln1b, XN);

        // QKV + fused head-split (Q scaled by dh^-0.5)
        tc_gemm_kernel<6,false><<<dim3(6, 128), 256>>>(XN, p_wqkv, Q, K, V,
            CB*CN, 3*CINNER, CD, 0, 0, 0, 0.f, nullptr, nullptr);

        landmark_kernel<<<(CBH*CML*CDH)/256, 256>>>(Q, K, QL, KL);

        // attn2 = softmax(QL @ KL^T)
        tc_gemm_kernel<0,true><<<dim3(2, 2, CBH), 256>>>(QL, KL, A2, nullptr, nullptr,
            CML, CML, CDH, SXD, SXD, MM, 0.f, nullptr, nullptr);
        softmax256_kernel<<<(CBH*CML)/8, 256>>>(A2);

        // pinv: 4 bf16 iterations + 1 tf32 cleanup iteration
        cudaMemsetAsync(G2, 0, sizeof(float));
        abs_colsum_max_kernel<<<CBH, 256>>>(A2);
        zinit_kernel<<<(int)((CBH*MM)/256), 256>>>(A2, Zb);

        float* zc = Zb; float* zn = Z2;
        for (int it = 0; it < 4; it++) {
            bf_gemm_kernel<3><<<dim3(2,2,CBH), 256>>>(A2, zc, XZ, T1, CML, CML, MM, 7.0f);
            bf_gemm_kernel<1><<<dim3(2,2,CBH), 256>>>(XZ, T1, T2, nullptr, CML, CML, MM, 15.0f);
            bf_gemm_kernel<1><<<dim3(2,2,CBH), 256>>>(XZ, T2, T1, nullptr, CML, CML, MM, 13.0f);
            bf_gemm_kernel<2><<<dim3(2,2,CBH), 256>>>(zc, T1, zn, nullptr, CML, CML, MM, 0.25f);
            float* t = zc; zc = zn; zn = t;
        }
        {
            tc_gemm_kernel<3,false><<<dim3(2,2,CBH), 256>>>(A2, zc, XZ, T1, nullptr,
                CML, CML, CML, MM, MM, MM, 7.0f, nullptr, nullptr);
            tc_gemm_kernel<1,false><<<dim3(2,2,CBH), 256>>>(XZ, T1, T2, nullptr, nullptr,
                CML, CML, CML, MM, MM, MM, 15.0f, nullptr, nullptr);
            tc_gemm_kernel<1,false><<<dim3(2,2,CBH), 256>>>(XZ, T2, T1, nullptr, nullptr,
                CML, CML, CML, MM, MM, MM, 13.0f, nullptr, nullptr);
            tc_gemm_kernel<2,false><<<dim3(2,2,CBH), 256>>>(zc, T1, zn, nullptr, nullptr,
                CML, CML, CML, MM, MM, MM, 0.25f, nullptr, nullptr);
            float* t = zc; zc = zn; zn = t;
        }

        // X1 = softmax(QL @ K^T) @ V  (split over 4 key-chunks + exact merge)
        fused_attn3_split_kernel<<<dim3(2, 4, CBH), 256, FUSED_SMEM>>>(
            QL, K, V, P3o, P3m, P3l);
        attn3_merge_kernel<<<(CBH*CML*CDH)/256, 256>>>(P3o, P3m, P3l, X1);

        // X2 = pinv @ X1
        tc_n32_kernel<<<dim3(2, 1, CBH), 256>>>(zc, X1, X2, CML, CML, MM, SXD, SXD);

        // OH = softmax(Q @ KL^T) @ X2  (fused)
        fused_attn1_kernel<<<dim3(32, CBH), 256, FUSED_SMEM>>>(Q, KL, X2, OH);

        // conv residual + head merge (fused)
        conv_merge_kernel<<<(CB*CN*CD)/256, 256>>>(OH, V, p_resw, ONBD);

        tc_gemm_kernel<4,false><<<dim3(2, 128), 256>>>(ONBD, p_wout, Y, nullptr, nullptr,
            CB*CN, CD, CINNER, 0, 0, 0, 0.f, p_bout, Y);

        layernorm_kernel<<<CB*CN, 256>>>(Y, p_ln2g, p_ln2b, XN);
        tc_gemm_kernel<5,false><<<dim3(4, 128), 256>>>(XN, p_w1, HID, nullptr, nullptr,
            CB*CN, 2*CD, CD, 0, 0, 0, 0.f, p_b1, nullptr);
        tc_gemm_kernel<4,false><<<dim3(2, 128), 256>>>(HID, p_w2, Y, nullptr, nullptr,
            CB*CN, CD, 2*CD, 0, 0, 0, 0.f, p_b2, Y);
    }

    cudaMemcpyAsync(d_out, Y, sizeof(float)*(size_t)CB*CN*CD, cudaMemcpyDeviceToDevice);
}